// round 16
// baseline (speedup 1.0000x reference)
#include <cuda_runtime.h>
#include <cuda_fp16.h>
#include <cstdint>
#include <math.h>

#define BATCH 16
#define SEQ   512
#define DIN   768
#define HID   256
#define ID    512
#define NST   16
#define RDT   16
#define KCONV 4
#define NCLS  2
#define MROWS (BATCH*SEQ)     /* 8192 */
#define KAUG  (DIN*9)         /* 6912 */
#define SSMW  (RDT+2*NST)     /* 48 */

// ---------------- scratch ----------------
__device__ __align__(128) __half g_augA[(size_t)MROWS*KAUG];
__device__ __align__(128) __half g_w1[(size_t)HID*KAUG];
__device__ __align__(128) float  g_h[MROWS*HID];
__device__ __align__(128) float  g_hp[3*MROWS*HID];    // split-K partials (up to 3)
__device__ __align__(128) __half g_xn[MROWS*HID];
__device__ __align__(128) float  g_p[(size_t)MROWS*2*ID];
__device__ __align__(128) float  g_u[(size_t)MROWS*ID];
__device__ __align__(128) float  g_s[(size_t)MROWS*SSMW];
__device__ __align__(128) __half g_y[(size_t)MROWS*ID];
__device__ __align__(128) __half g_ipw[2*2*ID*HID];
__device__ __align__(128) __half g_opw[2*HID*ID];
__device__ __align__(128) float  g_rs[MROWS];
__device__ __align__(128) float  g_emb[BATCH*2*HID];

// ---------------- helpers ----------------
__device__ __forceinline__ uint32_t smem_u32(const void* p) {
    uint32_t a;
    asm("{ .reg .u64 t; cvta.to.shared.u64 t, %1; cvt.u32.u64 %0, t; }" : "=r"(a) : "l"(p));
    return a;
}
__device__ __forceinline__ float siluf(float x) { return x / (1.0f + __expf(-x)); }

__device__ __forceinline__ void bspline8(float x, float* bas) {
    float b[11];
#pragma unroll
    for (int j = 0; j < 11; j++) {
        float g0 = (float)(j - 3) * 0.4f - 1.0f;
        float g1 = (float)(j - 2) * 0.4f - 1.0f;
        b[j] = (x >= g0 && x < g1) ? 1.0f : 0.0f;
    }
#pragma unroll
    for (int kk = 1; kk <= 3; kk++) {
        float inv = 1.0f / (0.4f * (float)kk);
#pragma unroll
        for (int j = 0; j < 11 - kk; j++) {
            float gj = (float)(j - 3) * 0.4f - 1.0f;
            float gk = (float)(j - 3 + kk + 1) * 0.4f - 1.0f;
            b[j] = (x - gj) * inv * b[j] + (gk - x) * inv * b[j + 1];
        }
    }
#pragma unroll
    for (int j = 0; j < 8; j++) bas[j] = b[j];
}

__device__ __forceinline__ float warp_sum(float v) {
#pragma unroll
    for (int o = 16; o; o >>= 1) v += __shfl_xor_sync(0xffffffffu, v, o);
    return v;
}

__device__ __forceinline__ void mma_f16(float* c, const uint32_t* a, const uint32_t* b) {
    asm volatile(
        "mma.sync.aligned.m16n8k16.row.col.f32.f16.f16.f32 "
        "{%0,%1,%2,%3}, {%4,%5,%6,%7}, {%8,%9}, {%0,%1,%2,%3};"
        : "+f"(c[0]), "+f"(c[1]), "+f"(c[2]), "+f"(c[3])
        : "r"(a[0]), "r"(a[1]), "r"(a[2]), "r"(a[3]), "r"(b[0]), "r"(b[1]));
}
__device__ __forceinline__ void ldm_x4(uint32_t* r, uint32_t addr) {
    asm volatile("ldmatrix.sync.aligned.m8n8.x4.shared.b16 {%0,%1,%2,%3}, [%4];"
                 : "=r"(r[0]), "=r"(r[1]), "=r"(r[2]), "=r"(r[3]) : "r"(addr));
}
__device__ __forceinline__ void ldm_x2(uint32_t* r, uint32_t addr) {
    asm volatile("ldmatrix.sync.aligned.m8n8.x2.shared.b16 {%0,%1}, [%2];"
                 : "=r"(r[0]), "=r"(r[1]) : "r"(addr));
}
__device__ __forceinline__ void cp16(uint32_t dst, const void* src) {
    asm volatile("cp.async.cg.shared.global [%0], [%1], 16;" :: "r"(dst), "l"(src));
}

// ---------------- fused prep: KAN1 aug + KAN1 wcat + ipw/opw fp16 ----------------
#define NAUG (MROWS*DIN)
#define NWC  (HID*DIN)
#define NIP  (2*2*ID*HID)
#define NOP  (2*HID*ID)

__global__ void k_prep(const float* __restrict__ x,
                       const float* __restrict__ bw, const float* __restrict__ sw,
                       const float* __restrict__ ss,
                       const float* __restrict__ ipw, const float* __restrict__ opw) {
    int idx = blockIdx.x * blockDim.x + threadIdx.x;
    if (idx < NAUG) {
        int row = idx / DIN, i = idx - row * DIN;
        float v = x[idx];
        float bas[8];
        bspline8(v, bas);
        size_t base = (size_t)row * KAUG;
        g_augA[base + i] = __float2half_rn(siluf(v));
#pragma unroll
        for (int t = 0; t < 8; t++)
            g_augA[base + (size_t)(1 + t) * DIN + i] = __float2half_rn(bas[t]);
    } else if (idx < NAUG + NWC) {
        int j = idx - NAUG;
        int n = j / DIN, i = j - n * DIN;
        size_t base = (size_t)n * KAUG;
        g_w1[base + i] = __float2half_rn(bw[j]);
        float sc = ss[j];
#pragma unroll
        for (int t = 0; t < 8; t++)
            g_w1[base + (size_t)(1 + t) * DIN + i] = __float2half_rn(sw[(size_t)j * 8 + t] * sc);
    } else if (idx < NAUG + NWC + NIP) {
        int j = idx - NAUG - NWC;
        g_ipw[j] = __float2half_rn(ipw[j]);
    } else if (idx < NAUG + NWC + NIP + NOP) {
        int j = idx - NAUG - NWC - NIP;
        g_opw[j] = __float2half_rn(opw[j]);
    }
}

// ---------------- warp-MMA GEMM (BM=128, BN=128, BK=32; 3-stage cp.async) ------------
#define A_PLANE (128*80)
#define W_PLANE (128*80)
#define STAGE   (A_PLANE + W_PLANE)
#define GEMM_SMEM (3*STAGE)

extern __shared__ char gsm[];

template <int EPI, int MINB>
__global__ void __launch_bounds__(256, MINB)
k_mma_gemm(const __half* __restrict__ A, int lda,
           const __half* __restrict__ W, int ldw,
           float* __restrict__ C, float* __restrict__ Cpart, int ldc,
           const float* __restrict__ Cres, int K) {
    int tid = threadIdx.x;
    int lane = tid & 31;
    int warp = tid >> 5;
    int wm = warp >> 2;
    int wn = warp & 3;
    int m0 = blockIdx.y * 128;
    int n0 = blockIdx.x * 128;
    int nc_total = K >> 5;
    int nc = nc_total / (int)gridDim.z;
    int c_begin = blockIdx.z * nc;
    int c_end = c_begin + nc;

    float acc[4][4][4];
#pragma unroll
    for (int i = 0; i < 4; i++)
#pragma unroll
        for (int j = 0; j < 4; j++)
#pragma unroll
            for (int q = 0; q < 4; q++) acc[i][j][q] = 0.0f;

    auto issue = [&](int c, int s) {
        int k0 = c << 5;
        char* sb = gsm + s * STAGE;
#pragma unroll
        for (int j = 0; j < 2; j++) {
            int u = tid + j * 256;
            int rr = u >> 2, cb = u & 3;
            cp16(smem_u32(sb + rr * 80 + cb * 16),
                 A + (size_t)(m0 + rr) * lda + k0 + cb * 8);
        }
#pragma unroll
        for (int j = 0; j < 2; j++) {
            int u = tid + j * 256;
            int rr = u >> 2, cb = u & 3;
            cp16(smem_u32(sb + A_PLANE + rr * 80 + cb * 16),
                 W + (size_t)(n0 + rr) * ldw + k0 + cb * 8);
        }
        asm volatile("cp.async.commit_group;" ::: "memory");
    };

    issue(c_begin, 0);
    if (nc > 1) issue(c_begin + 1, 1);

    for (int c = c_begin; c < c_end; c++) {
        int s = (c - c_begin) % 3;
        if (c + 1 < c_end) asm volatile("cp.async.wait_group 1;" ::: "memory");
        else               asm volatile("cp.async.wait_group 0;" ::: "memory");
        __syncthreads();
        uint32_t aB = smem_u32(gsm + s * STAGE);
        uint32_t wB = aB + A_PLANE;
#pragma unroll
        for (int ks = 0; ks < 2; ks++) {
            uint32_t fa[4][4], fw[4][2];
            uint32_t aoff = (uint32_t)((wm * 64 + (lane & 15)) * 80 + ks * 32 + ((lane >> 4) << 4));
            uint32_t woff = (uint32_t)((wn * 32 + (lane & 7)) * 80 + ks * 32 + (((lane >> 3) & 1) << 4));
#pragma unroll
            for (int mi = 0; mi < 4; mi++) ldm_x4(fa[mi], aB + aoff + mi * 16 * 80);
#pragma unroll
            for (int ni = 0; ni < 4; ni++) ldm_x2(fw[ni], wB + woff + ni * 8 * 80);
#pragma unroll
            for (int mi = 0; mi < 4; mi++)
#pragma unroll
                for (int ni = 0; ni < 4; ni++)
                    mma_f16(acc[mi][ni], fa[mi], fw[ni]);
        }
        if (c + 2 < c_end) issue(c + 2, (c + 2 - c_begin) % 3);
    }

    bool primary = (blockIdx.z == 0);
    float* outb = primary ? C : (Cpart + (size_t)(blockIdx.z - 1) * MROWS * ldc);
#pragma unroll
    for (int mi = 0; mi < 4; mi++)
#pragma unroll
        for (int ni = 0; ni < 4; ni++) {
            int row = m0 + wm * 64 + mi * 16 + (lane >> 2);
            int col = n0 + wn * 32 + ni * 8 + (lane & 3) * 2;
            float* dst = outb + (size_t)row * ldc + col;
            float2 v0 = make_float2(acc[mi][ni][0], acc[mi][ni][1]);
            float2 v1 = make_float2(acc[mi][ni][2], acc[mi][ni][3]);
            if (EPI == 1 && primary) {
                const float* rs = Cres + (size_t)row * ldc + col;
                float2 r0 = *(const float2*)rs;
                float2 r1 = *(const float2*)(rs + 8 * ldc);
                v0.x += r0.x; v0.y += r0.y; v1.x += r1.x; v1.y += r1.y;
            }
            *(float2*)dst = v0;
            *(float2*)(dst + 8 * ldc) = v1;
        }
}

// ---------------- SIMT GEMM (x_proj) ----------------
template <int BM, int BN, int BK, int TM, int TN>
__global__ void gemm_tn(const float* __restrict__ A, int lda,
                        const float* __restrict__ W, int ldw,
                        float* __restrict__ C, int ldc,
                        int M, int N, int K) {
    constexpr int THREADS = (BM / TM) * (BN / TN);
    __shared__ float As[BK][BM];
    __shared__ float Ws[BK][BN + 4];
    int tid = threadIdx.x;
    int tx = tid % (BN / TN);
    int ty = tid / (BN / TN);
    int m0 = blockIdx.x * BM;
    int n0 = blockIdx.y * BN;
    float acc[TM][TN];
#pragma unroll
    for (int i = 0; i < TM; i++)
#pragma unroll
        for (int j = 0; j < TN; j++) acc[i][j] = 0.0f;

    constexpr int A4 = BM * BK / 4;
    constexpr int W4 = BN * BK / 4;

    for (int k0 = 0; k0 < K; k0 += BK) {
#pragma unroll
        for (int q = tid; q < A4; q += THREADS) {
            int m = q >> 2;
            int kq = (q & 3) * 4;
            float4 v = *(const float4*)(A + (size_t)(m0 + m) * lda + k0 + kq);
            As[kq + 0][m] = v.x; As[kq + 1][m] = v.y;
            As[kq + 2][m] = v.z; As[kq + 3][m] = v.w;
        }
#pragma unroll
        for (int q = tid; q < W4; q += THREADS) {
            int n = q >> 2;
            int kq = (q & 3) * 4;
            float4 v = make_float4(0.f, 0.f, 0.f, 0.f);
            if (n0 + n < N) v = *(const float4*)(W + (size_t)(n0 + n) * ldw + k0 + kq);
            Ws[kq + 0][n] = v.x; Ws[kq + 1][n] = v.y;
            Ws[kq + 2][n] = v.z; Ws[kq + 3][n] = v.w;
        }
        __syncthreads();
#pragma unroll
        for (int kk = 0; kk < BK; kk++) {
            float af[TM], wf[TN];
#pragma unroll
            for (int i = 0; i < TM; i++) af[i] = As[kk][ty * TM + i];
#pragma unroll
            for (int j = 0; j < TN; j++) wf[j] = Ws[kk][tx * TN + j];
#pragma unroll
            for (int i = 0; i < TM; i++)
#pragma unroll
                for (int j = 0; j < TN; j++) acc[i][j] = fmaf(af[i], wf[j], acc[i][j]);
        }
        __syncthreads();
    }

#pragma unroll
    for (int i = 0; i < TM; i++) {
        int m = m0 + ty * TM + i;
#pragma unroll
        for (int j = 0; j < TN; j++) {
            int n = n0 + tx * TN + j;
            if (n < N) C[(size_t)m * ldc + n] = acc[i][j];
        }
    }
}

// ---------------- fused split-K(4)-reduce + layernorm + layer0 rmsnorm ----------------
__global__ void k_lnrms(float* __restrict__ buf, const float* __restrict__ parts,
                        const float* __restrict__ g, const float* __restrict__ bb,
                        __half* __restrict__ xn, const float* __restrict__ w0) {
    __shared__ float sh[8];
    int row = blockIdx.x, t = threadIdx.x;
    size_t o = (size_t)row * HID + t;
    float v = buf[o] + parts[o] + parts[o + (size_t)MROWS * HID] + parts[o + 2 * (size_t)MROWS * HID];
    float s = warp_sum(v);
    if ((t & 31) == 0) sh[t >> 5] = s;
    __syncthreads();
    float mean = (sh[0] + sh[1] + sh[2] + sh[3] + sh[4] + sh[5] + sh[6] + sh[7]) * (1.0f / HID);
    __syncthreads();
    float d = v - mean;
    float s2 = warp_sum(d * d);
    if ((t & 31) == 0) sh[t >> 5] = s2;
    __syncthreads();
    float var = (sh[0] + sh[1] + sh[2] + sh[3] + sh[4] + sh[5] + sh[6] + sh[7]) * (1.0f / HID);
    float o2 = d * rsqrtf(var + 1e-5f) * g[t] + bb[t];
    buf[o] = o2;
    __syncthreads();
    float s3 = warp_sum(o2 * o2);
    if ((t & 31) == 0) sh[t >> 5] = s3;
    __syncthreads();
    float ms = (sh[0] + sh[1] + sh[2] + sh[3] + sh[4] + sh[5] + sh[6] + sh[7]) * (1.0f / HID);
    xn[o] = __float2half_rn(w0[t] * o2 * rsqrtf(ms + 1e-5f));
}

__global__ void k_rmsnorm_h(const float* __restrict__ src, __half* __restrict__ dst,
                            const float* __restrict__ w) {
    __shared__ float sh[8];
    int row = blockIdx.x, t = threadIdx.x;
    float v = src[(size_t)row * HID + t];
    float s2 = warp_sum(v * v);
    if ((t & 31) == 0) sh[t >> 5] = s2;
    __syncthreads();
    float ms = (sh[0] + sh[1] + sh[2] + sh[3] + sh[4] + sh[5] + sh[6] + sh[7]) * (1.0f / HID);
    dst[(size_t)row * HID + t] = __float2half_rn(w[t] * v * rsqrtf(ms + 1e-5f));
}

__global__ void k_rmsscale(const float* __restrict__ src, float* __restrict__ scale) {
    __shared__ float sh[8];
    int row = blockIdx.x, t = threadIdx.x;
    float v = src[(size_t)row * HID + t];
    float s2 = warp_sum(v * v);
    if ((t & 31) == 0) sh[t >> 5] = s2;
    __syncthreads();
    if (t == 0) {
        float ms = (sh[0] + sh[1] + sh[2] + sh[3] + sh[4] + sh[5] + sh[6] + sh[7]) * (1.0f / HID);
        scale[row] = rsqrtf(ms + 1e-5f);
    }
}

// ---------------- causal depthwise conv (K=4) + SiLU ----------------
__global__ void k_conv(const float* __restrict__ cw, const float* __restrict__ cb) {
    int idx = blockIdx.x * blockDim.x + threadIdx.x;
    if (idx >= MROWS * ID) return;
    int i = idx & (ID - 1);
    int row = idx >> 9;
    int l = row & (SEQ - 1);
    float acc = cb[i];
#pragma unroll
    for (int k = 0; k < KCONV; k++) {
        int l2 = l - (KCONV - 1) + k;
        if (l2 >= 0)
            acc = fmaf(g_p[(size_t)(row - (KCONV - 1) + k) * (2 * ID) + i], cw[i * KCONV + k], acc);
    }
    g_u[idx] = siluf(acc);
}

// ---------------- selective scan with fused dt: thread per (b,i,ng) -----------------
// dt = softplus(s[:, :16] . dtw[i] + dtb[i]) computed in-register via 4-thread group dot
struct ScanBuf {
    float4 u, g;
    float4 D[4], B[4], C[4];   // dt_r quarters, B, C
};

__global__ void __launch_bounds__(128)
k_scan(const float* __restrict__ alog, const float* __restrict__ Dp,
       const float* __restrict__ dtw, const float* __restrict__ dtb) {
    int t = blockIdx.x * blockDim.x + threadIdx.x;
    int ng = t & 3;
    int i = (t >> 2) & (ID - 1);
    int b = t >> 11;

    float4 al = *(const float4*)(alog + i * NST + 4 * ng);
    float A0 = -__expf(al.x), A1 = -__expf(al.y), A2 = -__expf(al.z), A3 = -__expf(al.w);
    float Dv = Dp[i];
    float4 wdt = *(const float4*)(dtw + i * RDT + 4 * ng);
    float bdt = dtb[i];

    const float* up  = g_u + (size_t)b * SEQ * ID + i;
    const float* sp0 = g_s + (size_t)b * SEQ * SSMW + 4 * ng;  // dt_r quarter
    const float* gp  = g_p + (size_t)b * SEQ * 2 * ID + ID + i;
    __half* yp       = g_y + (size_t)b * SEQ * ID + i;

    float s0 = 0.f, s1 = 0.f, s2 = 0.f, s3 = 0.f;

    auto load = [&](ScanBuf& bf, int lb) {
#pragma unroll
        for (int q = 0; q < 4; q++) {
            bf.D[q] = *(const float4*)(sp0 + (lb + q) * SSMW);
            bf.B[q] = *(const float4*)(sp0 + (lb + q) * SSMW + RDT);
            bf.C[q] = *(const float4*)(sp0 + (lb + q) * SSMW + RDT + NST);
        }
        bf.u.x = up[(lb + 0) * ID]; bf.u.y = up[(lb + 1) * ID];
        bf.u.z = up[(lb + 2) * ID]; bf.u.w = up[(lb + 3) * ID];
        if (ng == 0) {
            bf.g.x = gp[(size_t)(lb + 0) * 2 * ID]; bf.g.y = gp[(size_t)(lb + 1) * 2 * ID];
            bf.g.z = gp[(size_t)(lb + 2) * 2 * ID]; bf.g.w = gp[(size_t)(lb + 3) * 2 * ID];
        }
    };

    auto step4 = [&](const ScanBuf& bf, int lb) {
        float us[4] = { bf.u.x, bf.u.y, bf.u.z, bf.u.w };
        float gs[4] = { bf.g.x, bf.g.y, bf.g.z, bf.g.w };
#pragma unroll
        for (int q = 0; q < 4; q++) {
            // fused dt: group dot of dt_r quarters with dtw quarters
            float4 Dq = bf.D[q];
            float pd = Dq.x * wdt.x + Dq.y * wdt.y + Dq.z * wdt.z + Dq.w * wdt.w;
            pd += __shfl_xor_sync(0xffffffffu, pd, 1);
            pd += __shfl_xor_sync(0xffffffffu, pd, 2);
            float xdt = pd + bdt;
            float dtv = fmaxf(xdt, 0.0f) + log1pf(__expf(-fabsf(xdt)));  // softplus
            float uv = us[q];
            float4 Bv = bf.B[q], Cv = bf.C[q];
            float du = dtv * uv;
            s0 = fmaf(s0, __expf(dtv * A0), du * Bv.x);
            s1 = fmaf(s1, __expf(dtv * A1), du * Bv.y);
            s2 = fmaf(s2, __expf(dtv * A2), du * Bv.z);
            s3 = fmaf(s3, __expf(dtv * A3), du * Bv.w);
            float p = s0 * Cv.x + s1 * Cv.y + s2 * Cv.z + s3 * Cv.w;
            p += __shfl_xor_sync(0xffffffffu, p, 1);
            p += __shfl_xor_sync(0xffffffffu, p, 2);
            if (ng == 0)
                yp[(size_t)(lb + q) * ID] = __float2half_rn((p + uv * Dv) * siluf(gs[q]));
        }
    };

    ScanBuf ba, bb;
    load(ba, 0);
    for (int lb = 0; lb < SEQ; lb += 8) {
        load(bb, lb + 4);
        step4(ba, lb);
        if (lb + 8 < SEQ) load(ba, lb + 8);
        step4(bb, lb + 4);
    }
}

// ---------------- pooling with fused final rmsnorm ----------------
__global__ void k_pool(const float* __restrict__ h, const float* __restrict__ scale,
                       const float* __restrict__ nfw, float* __restrict__ out, int out_size) {
    int b = blockIdx.x;
    int j = threadIdx.x;
    int col = (j < HID) ? j : j - HID;
    float w = nfw[col];
    float sm = 0.0f, mx = -INFINITY;
    for (int l = 0; l < SEQ; l++) {
        int row = b * SEQ + l;
        float v = w * h[(size_t)row * HID + col] * scale[row];
        sm += v;
        mx = fmaxf(mx, v);
    }
    float r = (j < HID) ? sm * (1.0f / SEQ) : mx;
    g_emb[b * 2 * HID + j] = r;
    int oidx = NCLS * BATCH + b * 2 * HID + j;
    if (oidx < out_size) out[oidx] = r;
}

// ---------------- KAN head ----------------
__global__ void k_head(const float* __restrict__ bw2, const float* __restrict__ sw2,
                       const float* __restrict__ ss2, float* __restrict__ out) {
    __shared__ float r0[128], r1[128];
    int b = blockIdx.x;
    int tid = threadIdx.x;
    float p0 = 0.0f, p1 = 0.0f;
    for (int i = tid; i < 2 * HID; i += 128) {
        float e = g_emb[b * 2 * HID + i];
        float se = siluf(e);
        float bas[8];
        bspline8(e, bas);
        float s0 = se * bw2[i];
        float s1 = se * bw2[2 * HID + i];
        float sc0 = ss2[i], sc1 = ss2[2 * HID + i];
#pragma unroll
        for (int t = 0; t < 8; t++) {
            s0 = fmaf(bas[t] * sc0, sw2[(size_t)i * 8 + t], s0);
            s1 = fmaf(bas[t] * sc1, sw2[(size_t)(2 * HID + i) * 8 + t], s1);
        }
        p0 += s0;
        p1 += s1;
    }
    r0[tid] = p0;
    r1[tid] = p1;
    __syncthreads();
    for (int s = 64; s > 0; s >>= 1) {
        if (tid < s) { r0[tid] += r0[tid + s]; r1[tid] += r1[tid + s]; }
        __syncthreads();
    }
    if (tid == 0) {
        out[b * NCLS + 0] = r0[0];
        out[b * NCLS + 1] = r1[0];
    }
}

// ---------------- host ----------------
extern "C" void kernel_launch(void* const* d_in, const int* in_sizes, int n_in,
                              void* d_out, int out_size) {
    const float* x    = (const float*)d_in[0];
    const float* bw1  = (const float*)d_in[1];
    const float* sw1  = (const float*)d_in[2];
    const float* ss1  = (const float*)d_in[3];
    const float* ln_g = (const float*)d_in[4];
    const float* ln_b = (const float*)d_in[5];
    const float* nw   = (const float*)d_in[6];
    const float* ipw  = (const float*)d_in[7];
    const float* cw   = (const float*)d_in[8];
    const float* cb   = (const float*)d_in[9];
    const float* xpw  = (const float*)d_in[10];
    const float* dtw  = (const float*)d_in[11];
    const float* dtb  = (const float*)d_in[12];
    const float* alog = (const float*)d_in[13];
    const float* dpar = (const float*)d_in[14];
    const float* opw  = (const float*)d_in[15];
    const float* nfw  = (const float*)d_in[16];
    const float* bw2  = (const float*)d_in[17];
    const float* sw2  = (const float*)d_in[18];
    const float* ss2  = (const float*)d_in[19];
    float* out = (float*)d_out;

    __half *aA, *w1, *xn, *y, *ipwh, *opwh;
    float *h, *hp, *p, *u, *s, *rs;
    cudaGetSymbolAddress((void**)&aA, g_augA);
    cudaGetSymbolAddress((void**)&w1, g_w1);
    cudaGetSymbolAddress((void**)&xn, g_xn);
    cudaGetSymbolAddress((void**)&y, g_y);
    cudaGetSymbolAddress((void**)&ipwh, g_ipw);
    cudaGetSymbolAddress((void**)&opwh, g_opw);
    cudaGetSymbolAddress((void**)&h, g_h);
    cudaGetSymbolAddress((void**)&hp, g_hp);
    cudaGetSymbolAddress((void**)&p, g_p);
    cudaGetSymbolAddress((void**)&u, g_u);
    cudaGetSymbolAddress((void**)&s, g_s);
    cudaGetSymbolAddress((void**)&rs, g_rs);

    static bool attr_done = false;
    if (!attr_done) {
        cudaFuncSetAttribute((const void*)k_mma_gemm<0, 2>, cudaFuncAttributeMaxDynamicSharedMemorySize, GEMM_SMEM);
        cudaFuncSetAttribute((const void*)k_mma_gemm<1, 1>, cudaFuncAttributeMaxDynamicSharedMemorySize, GEMM_SMEM);
        attr_done = true;
    }

    // fused prep (aug + wcat + weight conversions)
    int nprep = NAUG + NWC + NIP + NOP;
    k_prep<<<(nprep + 255) / 256, 256>>>(x, bw1, sw1, ss1, ipw, opw);

    // KAN1 GEMM: split-K=4, occupancy-2; 3 partials reduced inside k_lnrms
    k_mma_gemm<0, 2><<<dim3(HID / 128, MROWS / 128, 4), 256, GEMM_SMEM>>>(
        aA, KAUG, w1, KAUG, h, hp, HID, nullptr, KAUG);
    k_lnrms<<<MROWS, HID>>>(h, hp, ln_g, ln_b, xn, nw);

    for (int layer = 0; layer < 2; layer++) {
        if (layer > 0)
            k_rmsnorm_h<<<MROWS, HID>>>(h, xn, nw + layer * HID);
        k_mma_gemm<0, 2><<<dim3((2 * ID) / 128, MROWS / 128, 1), 256, GEMM_SMEM>>>(
            xn, HID, ipwh + (size_t)layer * 2 * ID * HID, HID, p, nullptr, 2 * ID, nullptr, HID);
        k_conv<<<(MROWS * ID + 255) / 256, 256>>>(cw + layer * ID * KCONV, cb + layer * ID);
        gemm_tn<64, 64, 16, 4, 4><<<dim3(MROWS / 64, 1), 256>>>(
            u, ID, xpw + (size_t)layer * SSMW * ID, ID, s, SSMW, MROWS, SSMW, ID);
        // scan with fused dt-projection + softplus
        k_scan<<<(BATCH * ID * 4) / 128, 128>>>(
            alog + (size_t)layer * ID * NST, dpar + layer * ID,
            dtw + (size_t)layer * ID * RDT, dtb + (size_t)layer * ID);
        k_mma_gemm<1, 1><<<dim3(HID / 128, MROWS / 128, 1), 256, GEMM_SMEM>>>(
            y, ID, opwh + (size_t)layer * HID * ID, ID, h, nullptr, HID, h, ID);
    }

    k_rmsscale<<<MROWS, HID>>>(h, rs);
    k_pool<<<BATCH, 2 * HID>>>(h, rs, nfw, out, out_size);
    k_head<<<BATCH, 128>>>(bw2, sw2, ss2, out);
}

// round 17
// speedup vs baseline: 1.1210x; 1.1210x over previous
#include <cuda_runtime.h>
#include <cuda_fp16.h>
#include <cstdint>
#include <math.h>

#define BATCH 16
#define SEQ   512
#define DIN   768
#define HID   256
#define ID    512
#define NST   16
#define RDT   16
#define KCONV 4
#define NCLS  2
#define MROWS (BATCH*SEQ)     /* 8192 */
#define KAUG  (DIN*9)         /* 6912 */
#define SSMW  (RDT+2*NST)     /* 48 */

// ---------------- scratch ----------------
__device__ __align__(128) __half g_augA[(size_t)MROWS*KAUG];
__device__ __align__(128) __half g_w1[(size_t)HID*KAUG];
__device__ __align__(128) float  g_h[MROWS*HID];
__device__ __align__(128) float  g_hp[MROWS*HID];      // split-K partial
__device__ __align__(128) __half g_xn[MROWS*HID];
__device__ __align__(128) float  g_p[(size_t)MROWS*2*ID];
__device__ __align__(128) float  g_u[(size_t)MROWS*ID];
__device__ __align__(128) float  g_s[(size_t)MROWS*SSMW];
__device__ __align__(128) float  g_dt[(size_t)MROWS*ID];
__device__ __align__(128) __half g_y[(size_t)MROWS*ID];
__device__ __align__(128) __half g_ipw[2*2*ID*HID];
__device__ __align__(128) __half g_opw[2*HID*ID];
__device__ __align__(128) float  g_rs[MROWS];
__device__ __align__(128) float  g_emb[BATCH*2*HID];

// ---------------- helpers ----------------
__device__ __forceinline__ uint32_t smem_u32(const void* p) {
    uint32_t a;
    asm("{ .reg .u64 t; cvta.to.shared.u64 t, %1; cvt.u32.u64 %0, t; }" : "=r"(a) : "l"(p));
    return a;
}
__device__ __forceinline__ float siluf(float x) { return x / (1.0f + __expf(-x)); }

__device__ __forceinline__ void bspline8(float x, float* bas) {
    float b[11];
#pragma unroll
    for (int j = 0; j < 11; j++) {
        float g0 = (float)(j - 3) * 0.4f - 1.0f;
        float g1 = (float)(j - 2) * 0.4f - 1.0f;
        b[j] = (x >= g0 && x < g1) ? 1.0f : 0.0f;
    }
#pragma unroll
    for (int kk = 1; kk <= 3; kk++) {
        float inv = 1.0f / (0.4f * (float)kk);
#pragma unroll
        for (int j = 0; j < 11 - kk; j++) {
            float gj = (float)(j - 3) * 0.4f - 1.0f;
            float gk = (float)(j - 3 + kk + 1) * 0.4f - 1.0f;
            b[j] = (x - gj) * inv * b[j] + (gk - x) * inv * b[j + 1];
        }
    }
#pragma unroll
    for (int j = 0; j < 8; j++) bas[j] = b[j];
}

__device__ __forceinline__ float warp_sum(float v) {
#pragma unroll
    for (int o = 16; o; o >>= 1) v += __shfl_xor_sync(0xffffffffu, v, o);
    return v;
}

__device__ __forceinline__ void mma_f16(float* c, const uint32_t* a, const uint32_t* b) {
    asm volatile(
        "mma.sync.aligned.m16n8k16.row.col.f32.f16.f16.f32 "
        "{%0,%1,%2,%3}, {%4,%5,%6,%7}, {%8,%9}, {%0,%1,%2,%3};"
        : "+f"(c[0]), "+f"(c[1]), "+f"(c[2]), "+f"(c[3])
        : "r"(a[0]), "r"(a[1]), "r"(a[2]), "r"(a[3]), "r"(b[0]), "r"(b[1]));
}
__device__ __forceinline__ void ldm_x4(uint32_t* r, uint32_t addr) {
    asm volatile("ldmatrix.sync.aligned.m8n8.x4.shared.b16 {%0,%1,%2,%3}, [%4];"
                 : "=r"(r[0]), "=r"(r[1]), "=r"(r[2]), "=r"(r[3]) : "r"(addr));
}
__device__ __forceinline__ void ldm_x2(uint32_t* r, uint32_t addr) {
    asm volatile("ldmatrix.sync.aligned.m8n8.x2.shared.b16 {%0,%1}, [%2];"
                 : "=r"(r[0]), "=r"(r[1]) : "r"(addr));
}
__device__ __forceinline__ void cp16(uint32_t dst, const void* src) {
    asm volatile("cp.async.cg.shared.global [%0], [%1], 16;" :: "r"(dst), "l"(src));
}

// ---------------- fused prep: KAN1 aug + KAN1 wcat + ipw/opw fp16 ----------------
#define NAUG (MROWS*DIN)
#define NWC  (HID*DIN)
#define NIP  (2*2*ID*HID)
#define NOP  (2*HID*ID)

__global__ void k_prep(const float* __restrict__ x,
                       const float* __restrict__ bw, const float* __restrict__ sw,
                       const float* __restrict__ ss,
                       const float* __restrict__ ipw, const float* __restrict__ opw) {
    int idx = blockIdx.x * blockDim.x + threadIdx.x;
    if (idx < NAUG) {
        int row = idx / DIN, i = idx - row * DIN;
        float v = x[idx];
        float bas[8];
        bspline8(v, bas);
        size_t base = (size_t)row * KAUG;
        g_augA[base + i] = __float2half_rn(siluf(v));
#pragma unroll
        for (int t = 0; t < 8; t++)
            g_augA[base + (size_t)(1 + t) * DIN + i] = __float2half_rn(bas[t]);
    } else if (idx < NAUG + NWC) {
        int j = idx - NAUG;
        int n = j / DIN, i = j - n * DIN;
        size_t base = (size_t)n * KAUG;
        g_w1[base + i] = __float2half_rn(bw[j]);
        float sc = ss[j];
#pragma unroll
        for (int t = 0; t < 8; t++)
            g_w1[base + (size_t)(1 + t) * DIN + i] = __float2half_rn(sw[(size_t)j * 8 + t] * sc);
    } else if (idx < NAUG + NWC + NIP) {
        int j = idx - NAUG - NWC;
        g_ipw[j] = __float2half_rn(ipw[j]);
    } else if (idx < NAUG + NWC + NIP + NOP) {
        int j = idx - NAUG - NWC - NIP;
        g_opw[j] = __float2half_rn(opw[j]);
    }
}

// ---------------- warp-MMA GEMM (BM=128, BN=128, BK=32; 3-stage cp.async) ------------
// Optional split-K via gridDim.z: z=0 writes C (+Cres if EPI=1), z=1 writes Cpart.
#define A_PLANE (128*80)
#define W_PLANE (128*80)
#define STAGE   (A_PLANE + W_PLANE)
#define GEMM_SMEM (3*STAGE)

extern __shared__ char gsm[];

template <int EPI, int MINB>
__global__ void __launch_bounds__(256, MINB)
k_mma_gemm(const __half* __restrict__ A, int lda,
           const __half* __restrict__ W, int ldw,
           float* __restrict__ C, float* __restrict__ Cpart, int ldc,
           const float* __restrict__ Cres, int K) {
    int tid = threadIdx.x;
    int lane = tid & 31;
    int warp = tid >> 5;
    int wm = warp >> 2;
    int wn = warp & 3;
    int m0 = blockIdx.y * 128;
    int n0 = blockIdx.x * 128;
    int nc_total = K >> 5;
    int nc = nc_total / (int)gridDim.z;
    int c_begin = blockIdx.z * nc;
    int c_end = c_begin + nc;

    float acc[4][4][4];
#pragma unroll
    for (int i = 0; i < 4; i++)
#pragma unroll
        for (int j = 0; j < 4; j++)
#pragma unroll
            for (int q = 0; q < 4; q++) acc[i][j][q] = 0.0f;

    auto issue = [&](int c, int s) {
        int k0 = c << 5;
        char* sb = gsm + s * STAGE;
#pragma unroll
        for (int j = 0; j < 2; j++) {
            int u = tid + j * 256;
            int rr = u >> 2, cb = u & 3;
            cp16(smem_u32(sb + rr * 80 + cb * 16),
                 A + (size_t)(m0 + rr) * lda + k0 + cb * 8);
        }
#pragma unroll
        for (int j = 0; j < 2; j++) {
            int u = tid + j * 256;
            int rr = u >> 2, cb = u & 3;
            cp16(smem_u32(sb + A_PLANE + rr * 80 + cb * 16),
                 W + (size_t)(n0 + rr) * ldw + k0 + cb * 8);
        }
        asm volatile("cp.async.commit_group;" ::: "memory");
    };

    issue(c_begin, 0);
    if (nc > 1) issue(c_begin + 1, 1);

    for (int c = c_begin; c < c_end; c++) {
        int s = (c - c_begin) % 3;
        if (c + 1 < c_end) asm volatile("cp.async.wait_group 1;" ::: "memory");
        else               asm volatile("cp.async.wait_group 0;" ::: "memory");
        __syncthreads();
        uint32_t aB = smem_u32(gsm + s * STAGE);
        uint32_t wB = aB + A_PLANE;
#pragma unroll
        for (int ks = 0; ks < 2; ks++) {
            uint32_t fa[4][4], fw[4][2];
            uint32_t aoff = (uint32_t)((wm * 64 + (lane & 15)) * 80 + ks * 32 + ((lane >> 4) << 4));
            uint32_t woff = (uint32_t)((wn * 32 + (lane & 7)) * 80 + ks * 32 + (((lane >> 3) & 1) << 4));
#pragma unroll
            for (int mi = 0; mi < 4; mi++) ldm_x4(fa[mi], aB + aoff + mi * 16 * 80);
#pragma unroll
            for (int ni = 0; ni < 4; ni++) ldm_x2(fw[ni], wB + woff + ni * 8 * 80);
#pragma unroll
            for (int mi = 0; mi < 4; mi++)
#pragma unroll
                for (int ni = 0; ni < 4; ni++)
                    mma_f16(acc[mi][ni], fa[mi], fw[ni]);
        }
        if (c + 2 < c_end) issue(c + 2, (c + 2 - c_begin) % 3);
    }

    bool primary = (blockIdx.z == 0);
    float* outb = primary ? C : Cpart;
#pragma unroll
    for (int mi = 0; mi < 4; mi++)
#pragma unroll
        for (int ni = 0; ni < 4; ni++) {
            int row = m0 + wm * 64 + mi * 16 + (lane >> 2);
            int col = n0 + wn * 32 + ni * 8 + (lane & 3) * 2;
            float* dst = outb + (size_t)row * ldc + col;
            float2 v0 = make_float2(acc[mi][ni][0], acc[mi][ni][1]);
            float2 v1 = make_float2(acc[mi][ni][2], acc[mi][ni][3]);
            if (EPI == 1 && primary) {
                const float* rs = Cres + (size_t)row * ldc + col;
                float2 r0 = *(const float2*)rs;
                float2 r1 = *(const float2*)(rs + 8 * ldc);
                v0.x += r0.x; v0.y += r0.y; v1.x += r1.x; v1.y += r1.y;
            }
            *(float2*)dst = v0;
            *(float2*)(dst + 8 * ldc) = v1;
        }
}

// ---------------- SIMT GEMM (small Mamba projections) ----------------
// EPI 0: none; 2: softplus(acc + bias[n])
template <int BM, int BN, int BK, int TM, int TN, int EPI>
__global__ void gemm_tn(const float* __restrict__ A, int lda,
                        const float* __restrict__ W, int ldw,
                        float* __restrict__ C, int ldc,
                        const float* __restrict__ bias,
                        int M, int N, int K) {
    constexpr int THREADS = (BM / TM) * (BN / TN);
    __shared__ float As[BK][BM];
    __shared__ float Ws[BK][BN + 4];
    int tid = threadIdx.x;
    int tx = tid % (BN / TN);
    int ty = tid / (BN / TN);
    int m0 = blockIdx.x * BM;
    int n0 = blockIdx.y * BN;
    float acc[TM][TN];
#pragma unroll
    for (int i = 0; i < TM; i++)
#pragma unroll
        for (int j = 0; j < TN; j++) acc[i][j] = 0.0f;

    constexpr int A4 = BM * BK / 4;
    constexpr int W4 = BN * BK / 4;

    for (int k0 = 0; k0 < K; k0 += BK) {
#pragma unroll
        for (int q = tid; q < A4; q += THREADS) {
            int m = q >> 2;
            int kq = (q & 3) * 4;
            float4 v = *(const float4*)(A + (size_t)(m0 + m) * lda + k0 + kq);
            As[kq + 0][m] = v.x; As[kq + 1][m] = v.y;
            As[kq + 2][m] = v.z; As[kq + 3][m] = v.w;
        }
#pragma unroll
        for (int q = tid; q < W4; q += THREADS) {
            int n = q >> 2;
            int kq = (q & 3) * 4;
            float4 v = make_float4(0.f, 0.f, 0.f, 0.f);
            if (n0 + n < N) v = *(const float4*)(W + (size_t)(n0 + n) * ldw + k0 + kq);
            Ws[kq + 0][n] = v.x; Ws[kq + 1][n] = v.y;
            Ws[kq + 2][n] = v.z; Ws[kq + 3][n] = v.w;
        }
        __syncthreads();
#pragma unroll
        for (int kk = 0; kk < BK; kk++) {
            float af[TM], wf[TN];
#pragma unroll
            for (int i = 0; i < TM; i++) af[i] = As[kk][ty * TM + i];
#pragma unroll
            for (int j = 0; j < TN; j++) wf[j] = Ws[kk][tx * TN + j];
#pragma unroll
            for (int i = 0; i < TM; i++)
#pragma unroll
                for (int j = 0; j < TN; j++) acc[i][j] = fmaf(af[i], wf[j], acc[i][j]);
        }
        __syncthreads();
    }

#pragma unroll
    for (int i = 0; i < TM; i++) {
        int m = m0 + ty * TM + i;
#pragma unroll
        for (int j = 0; j < TN; j++) {
            int n = n0 + tx * TN + j;
            if (n < N) {
                float v = acc[i][j];
                if (EPI == 2) {
                    v += bias[n];
                    v = fmaxf(v, 0.0f) + log1pf(__expf(-fabsf(v)));
                }
                C[(size_t)m * ldc + n] = v;
            }
        }
    }
}

// ---------------- fused split-K-reduce + layernorm + layer0 rmsnorm ----------------
__global__ void k_lnrms(float* __restrict__ buf, const float* __restrict__ part,
                        const float* __restrict__ g, const float* __restrict__ bb,
                        __half* __restrict__ xn, const float* __restrict__ w0) {
    __shared__ float sh[8];
    int row = blockIdx.x, t = threadIdx.x;
    size_t o = (size_t)row * HID + t;
    float v = buf[o] + part[o];
    float s = warp_sum(v);
    if ((t & 31) == 0) sh[t >> 5] = s;
    __syncthreads();
    float mean = (sh[0] + sh[1] + sh[2] + sh[3] + sh[4] + sh[5] + sh[6] + sh[7]) * (1.0f / HID);
    __syncthreads();
    float d = v - mean;
    float s2 = warp_sum(d * d);
    if ((t & 31) == 0) sh[t >> 5] = s2;
    __syncthreads();
    float var = (sh[0] + sh[1] + sh[2] + sh[3] + sh[4] + sh[5] + sh[6] + sh[7]) * (1.0f / HID);
    float o2 = d * rsqrtf(var + 1e-5f) * g[t] + bb[t];
    buf[o] = o2;
    __syncthreads();
    float s3 = warp_sum(o2 * o2);
    if ((t & 31) == 0) sh[t >> 5] = s3;
    __syncthreads();
    float ms = (sh[0] + sh[1] + sh[2] + sh[3] + sh[4] + sh[5] + sh[6] + sh[7]) * (1.0f / HID);
    xn[o] = __float2half_rn(w0[t] * o2 * rsqrtf(ms + 1e-5f));
}

__global__ void k_rmsnorm_h(const float* __restrict__ src, __half* __restrict__ dst,
                            const float* __restrict__ w) {
    __shared__ float sh[8];
    int row = blockIdx.x, t = threadIdx.x;
    float v = src[(size_t)row * HID + t];
    float s2 = warp_sum(v * v);
    if ((t & 31) == 0) sh[t >> 5] = s2;
    __syncthreads();
    float ms = (sh[0] + sh[1] + sh[2] + sh[3] + sh[4] + sh[5] + sh[6] + sh[7]) * (1.0f / HID);
    dst[(size_t)row * HID + t] = __float2half_rn(w[t] * v * rsqrtf(ms + 1e-5f));
}

__global__ void k_rmsscale(const float* __restrict__ src, float* __restrict__ scale) {
    __shared__ float sh[8];
    int row = blockIdx.x, t = threadIdx.x;
    float v = src[(size_t)row * HID + t];
    float s2 = warp_sum(v * v);
    if ((t & 31) == 0) sh[t >> 5] = s2;
    __syncthreads();
    if (t == 0) {
        float ms = (sh[0] + sh[1] + sh[2] + sh[3] + sh[4] + sh[5] + sh[6] + sh[7]) * (1.0f / HID);
        scale[row] = rsqrtf(ms + 1e-5f);
    }
}

// ---------------- causal depthwise conv (K=4) + SiLU ----------------
__global__ void k_conv(const float* __restrict__ cw, const float* __restrict__ cb) {
    int idx = blockIdx.x * blockDim.x + threadIdx.x;
    if (idx >= MROWS * ID) return;
    int i = idx & (ID - 1);
    int row = idx >> 9;
    int l = row & (SEQ - 1);
    float acc = cb[i];
#pragma unroll
    for (int k = 0; k < KCONV; k++) {
        int l2 = l - (KCONV - 1) + k;
        if (l2 >= 0)
            acc = fmaf(g_p[(size_t)(row - (KCONV - 1) + k) * (2 * ID) + i], cw[i * KCONV + k], acc);
    }
    g_u[idx] = siluf(acc);
}

// ---------------- selective scan: thread per (b,i,ng); register double buffer -------
struct ScanBuf {
    float4 dt, u, g;
    float4 B[4], C[4];
};

__global__ void __launch_bounds__(128)
k_scan(const float* __restrict__ alog, const float* __restrict__ Dp) {
    int t = blockIdx.x * blockDim.x + threadIdx.x;
    int ng = t & 3;
    int i = (t >> 2) & (ID - 1);
    int b = t >> 11;

    float4 al = *(const float4*)(alog + i * NST + 4 * ng);
    float A0 = -__expf(al.x), A1 = -__expf(al.y), A2 = -__expf(al.z), A3 = -__expf(al.w);
    float Dv = Dp[i];

    const float* dtp = g_dt + (size_t)b * SEQ * ID + i;
    const float* up  = g_u  + (size_t)b * SEQ * ID + i;
    const float* sp  = g_s  + (size_t)b * SEQ * SSMW + RDT + 4 * ng;
    const float* gp  = g_p  + (size_t)b * SEQ * 2 * ID + ID + i;
    __half* yp       = g_y  + (size_t)b * SEQ * ID + i;

    float s0 = 0.f, s1 = 0.f, s2 = 0.f, s3 = 0.f;

    auto load = [&](ScanBuf& bf, int lb) {
#pragma unroll
        for (int q = 0; q < 4; q++) {
            bf.B[q] = *(const float4*)(sp + (lb + q) * SSMW);
            bf.C[q] = *(const float4*)(sp + (lb + q) * SSMW + NST);
        }
        bf.dt.x = dtp[(lb + 0) * ID]; bf.dt.y = dtp[(lb + 1) * ID];
        bf.dt.z = dtp[(lb + 2) * ID]; bf.dt.w = dtp[(lb + 3) * ID];
        bf.u.x = up[(lb + 0) * ID]; bf.u.y = up[(lb + 1) * ID];
        bf.u.z = up[(lb + 2) * ID]; bf.u.w = up[(lb + 3) * ID];
        if (ng == 0) {
            bf.g.x = gp[(size_t)(lb + 0) * 2 * ID]; bf.g.y = gp[(size_t)(lb + 1) * 2 * ID];
            bf.g.z = gp[(size_t)(lb + 2) * 2 * ID]; bf.g.w = gp[(size_t)(lb + 3) * 2 * ID];
        }
    };

    auto step4 = [&](const ScanBuf& bf, int lb) {
        float dts[4] = { bf.dt.x, bf.dt.y, bf.dt.z, bf.dt.w };
        float us[4]  = { bf.u.x,  bf.u.y,  bf.u.z,  bf.u.w };
        float gs[4]  = { bf.g.x,  bf.g.y,  bf.g.z,  bf.g.w };
#pragma unroll
        for (int q = 0; q < 4; q++) {
            float dtv = dts[q], uv = us[q];
            float4 Bv = bf.B[q], Cv = bf.C[q];
            float du = dtv * uv;
            s0 = fmaf(s0, __expf(dtv * A0), du * Bv.x);
            s1 = fmaf(s1, __expf(dtv * A1), du * Bv.y);
            s2 = fmaf(s2, __expf(dtv * A2), du * Bv.z);
            s3 = fmaf(s3, __expf(dtv * A3), du * Bv.w);
            float p = s0 * Cv.x + s1 * Cv.y + s2 * Cv.z + s3 * Cv.w;
            p += __shfl_xor_sync(0xffffffffu, p, 1);
            p += __shfl_xor_sync(0xffffffffu, p, 2);
            if (ng == 0)
                yp[(size_t)(lb + q) * ID] = __float2half_rn((p + uv * Dv) * siluf(gs[q]));
        }
    };

    ScanBuf ba, bb;
    load(ba, 0);
    for (int lb = 0; lb < SEQ; lb += 8) {
        load(bb, lb + 4);
        step4(ba, lb);
        if (lb + 8 < SEQ) load(ba, lb + 8);
        step4(bb, lb + 4);
    }
}

// ---------------- pooling with fused final rmsnorm ----------------
__global__ void k_pool(const float* __restrict__ h, const float* __restrict__ scale,
                       const float* __restrict__ nfw, float* __restrict__ out, int out_size) {
    int b = blockIdx.x;
    int j = threadIdx.x;
    int col = (j < HID) ? j : j - HID;
    float w = nfw[col];
    float sm = 0.0f, mx = -INFINITY;
    for (int l = 0; l < SEQ; l++) {
        int row = b * SEQ + l;
        float v = w * h[(size_t)row * HID + col] * scale[row];
        sm += v;
        mx = fmaxf(mx, v);
    }
    float r = (j < HID) ? sm * (1.0f / SEQ) : mx;
    g_emb[b * 2 * HID + j] = r;
    int oidx = NCLS * BATCH + b * 2 * HID + j;
    if (oidx < out_size) out[oidx] = r;
}

// ---------------- KAN head ----------------
__global__ void k_head(const float* __restrict__ bw2, const float* __restrict__ sw2,
                       const float* __restrict__ ss2, float* __restrict__ out) {
    __shared__ float r0[128], r1[128];
    int b = blockIdx.x;
    int tid = threadIdx.x;
    float p0 = 0.0f, p1 = 0.0f;
    for (int i = tid; i < 2 * HID; i += 128) {
        float e = g_emb[b * 2 * HID + i];
        float se = siluf(e);
        float bas[8];
        bspline8(e, bas);
        float s0 = se * bw2[i];
        float s1 = se * bw2[2 * HID + i];
        float sc0 = ss2[i], sc1 = ss2[2 * HID + i];
#pragma unroll
        for (int t = 0; t < 8; t++) {
            s0 = fmaf(bas[t] * sc0, sw2[(size_t)i * 8 + t], s0);
            s1 = fmaf(bas[t] * sc1, sw2[(size_t)(2 * HID + i) * 8 + t], s1);
        }
        p0 += s0;
        p1 += s1;
    }
    r0[tid] = p0;
    r1[tid] = p1;
    __syncthreads();
    for (int s = 64; s > 0; s >>= 1) {
        if (tid < s) { r0[tid] += r0[tid + s]; r1[tid] += r1[tid + s]; }
        __syncthreads();
    }
    if (tid == 0) {
        out[b * NCLS + 0] = r0[0];
        out[b * NCLS + 1] = r1[0];
    }
}

// ---------------- host ----------------
extern "C" void kernel_launch(void* const* d_in, const int* in_sizes, int n_in,
                              void* d_out, int out_size) {
    const float* x    = (const float*)d_in[0];
    const float* bw1  = (const float*)d_in[1];
    const float* sw1  = (const float*)d_in[2];
    const float* ss1  = (const float*)d_in[3];
    const float* ln_g = (const float*)d_in[4];
    const float* ln_b = (const float*)d_in[5];
    const float* nw   = (const float*)d_in[6];
    const float* ipw  = (const float*)d_in[7];
    const float* cw   = (const float*)d_in[8];
    const float* cb   = (const float*)d_in[9];
    const float* xpw  = (const float*)d_in[10];
    const float* dtw  = (const float*)d_in[11];
    const float* dtb  = (const float*)d_in[12];
    const float* alog = (const float*)d_in[13];
    const float* dpar = (const float*)d_in[14];
    const float* opw  = (const float*)d_in[15];
    const float* nfw  = (const float*)d_in[16];
    const float* bw2  = (const float*)d_in[17];
    const float* sw2  = (const float*)d_in[18];
    const float* ss2  = (const float*)d_in[19];
    float* out = (float*)d_out;

    __half *aA, *w1, *xn, *y, *ipwh, *opwh;
    float *h, *hp, *p, *u, *s, *dt, *rs;
    cudaGetSymbolAddress((void**)&aA, g_augA);
    cudaGetSymbolAddress((void**)&w1, g_w1);
    cudaGetSymbolAddress((void**)&xn, g_xn);
    cudaGetSymbolAddress((void**)&y, g_y);
    cudaGetSymbolAddress((void**)&ipwh, g_ipw);
    cudaGetSymbolAddress((void**)&opwh, g_opw);
    cudaGetSymbolAddress((void**)&h, g_h);
    cudaGetSymbolAddress((void**)&hp, g_hp);
    cudaGetSymbolAddress((void**)&p, g_p);
    cudaGetSymbolAddress((void**)&u, g_u);
    cudaGetSymbolAddress((void**)&s, g_s);
    cudaGetSymbolAddress((void**)&dt, g_dt);
    cudaGetSymbolAddress((void**)&rs, g_rs);

    static bool attr_done = false;
    if (!attr_done) {
        cudaFuncSetAttribute((const void*)k_mma_gemm<0, 2>, cudaFuncAttributeMaxDynamicSharedMemorySize, GEMM_SMEM);
        cudaFuncSetAttribute((const void*)k_mma_gemm<1, 1>, cudaFuncAttributeMaxDynamicSharedMemorySize, GEMM_SMEM);
        attr_done = true;
    }

    // fused prep (aug + wcat + weight conversions)
    int nprep = NAUG + NWC + NIP + NOP;
    k_prep<<<(nprep + 255) / 256, 256>>>(x, bw1, sw1, ss1, ipw, opw);

    // KAN1 GEMM: split-K=2, occupancy-2; partial reduced inside k_lnrms
    k_mma_gemm<0, 2><<<dim3(HID / 128, MROWS / 128, 2), 256, GEMM_SMEM>>>(
        aA, KAUG, w1, KAUG, h, hp, HID, nullptr, KAUG);
    k_lnrms<<<MROWS, HID>>>(h, hp, ln_g, ln_b, xn, nw);

    for (int layer = 0; layer < 2; layer++) {
        if (layer > 0)
            k_rmsnorm_h<<<MROWS, HID>>>(h, xn, nw + layer * HID);
        // in_proj (occupancy-2)
        k_mma_gemm<0, 2><<<dim3((2 * ID) / 128, MROWS / 128, 1), 256, GEMM_SMEM>>>(
            xn, HID, ipwh + (size_t)layer * 2 * ID * HID, HID, p, nullptr, 2 * ID, nullptr, HID);
        k_conv<<<(MROWS * ID + 255) / 256, 256>>>(cw + layer * ID * KCONV, cb + layer * ID);
        // x_proj [SIMT]
        gemm_tn<64, 64, 16, 4, 4, 0><<<dim3(MROWS / 64, 1), 256>>>(
            u, ID, xpw + (size_t)layer * SSMW * ID, ID, s, SSMW,
            nullptr, MROWS, SSMW, ID);
        // dt GEMM + softplus epilogue [SIMT]
        gemm_tn<64, 64, 16, 4, 4, 2><<<dim3(MROWS / 64, ID / 64), 256>>>(
            s, SSMW, dtw + (size_t)layer * ID * RDT, RDT, dt, ID,
            dtb + layer * ID, MROWS, ID, RDT);
        k_scan<<<(BATCH * ID * 4) / 128, 128>>>(alog + (size_t)layer * ID * NST, dpar + layer * ID);
        // out_proj + residual (plain)
        k_mma_gemm<1, 1><<<dim3(HID / 128, MROWS / 128, 1), 256, GEMM_SMEM>>>(
            y, ID, opwh + (size_t)layer * HID * ID, ID, h, nullptr, HID, h, ID);
    }

    k_rmsscale<<<MROWS, HID>>>(h, rs);
    k_pool<<<BATCH, 2 * HID>>>(h, rs, nfw, out, out_size);
    k_head<<<BATCH, 128>>>(bw2, sw2, ss2, out);
}